// round 9
// baseline (speedup 1.0000x reference)
#include <cuda_runtime.h>
#include <cuda_fp16.h>
#include <cstdint>

// Problem constants
#define B_ 4
#define T_ 2048
#define DIM_ 2048
#define H_ 16
#define QLORA_ 1536
#define KVLORA_ 512
#define MTOK (B_ * T_)   // 8192

// ---------------- scratch (device globals; no runtime allocation) -------------
__device__ __half g_xh[(size_t)MTOK * DIM_];
__device__ __half g_cqh[(size_t)MTOK * QLORA_];
__device__ __half g_kvrawh[(size_t)MTOK * 576];
__device__ __half g_ckvh[(size_t)MTOK * KVLORA_];
__device__ __half g_qh[(size_t)MTOK * 3072];
__device__ __half g_kropeh[(size_t)MTOK * 64];
__device__ __half g_kvh[(size_t)MTOK * 4096];
__device__ __half g_attnoh[(size_t)MTOK * 2048];
__device__ __half g_wqd[(size_t)QLORA_ * DIM_];
__device__ __half g_wkd[(size_t)576 * DIM_];
__device__ __half g_wqu[(size_t)3072 * QLORA_];
__device__ __half g_wku[(size_t)4096 * KVLORA_];
__device__ __half g_wwo[(size_t)DIM_ * 2048];

// ---------------- helpers ------------------------------------------------------
__device__ __forceinline__ float block_reduce_sum_256(float v) {
    __shared__ float red[8];
    int lane = threadIdx.x & 31, w = threadIdx.x >> 5;
#pragma unroll
    for (int o = 16; o; o >>= 1) v += __shfl_xor_sync(0xffffffffu, v, o);
    if (lane == 0) red[w] = v;
    __syncthreads();
    if (w == 0) {
        v = (lane < 8) ? red[lane] : 0.f;
#pragma unroll
        for (int o = 4; o; o >>= 1) v += __shfl_xor_sync(0xffffffffu, v, o);
        if (lane == 0) red[0] = v;
    }
    __syncthreads();
    return red[0];
}

__device__ __forceinline__ float ex2(float x) {
    float r;
    asm("ex2.approx.ftz.f32 %0, %1;" : "=f"(r) : "f"(x));
    return r;
}
__device__ __forceinline__ uint32_t smem_u32(const void* p) {
    uint32_t a;
    asm("{ .reg .u64 t; cvta.to.shared.u64 t, %1; cvt.u32.u64 %0, t; }"
        : "=r"(a) : "l"(p));
    return a;
}
__device__ __forceinline__ uint32_t packh2(float a, float b) {
    __half2 h = __floats2half2_rn(a, b);
    return *(uint32_t*)&h;
}

#define LDMX4(r, addr) \
    asm volatile("ldmatrix.sync.aligned.m8n8.x4.shared.b16 {%0,%1,%2,%3}, [%4];" \
        : "=r"((r)[0]), "=r"((r)[1]), "=r"((r)[2]), "=r"((r)[3]) : "r"(addr))
#define LDMX4T(r, addr) \
    asm volatile("ldmatrix.sync.aligned.m8n8.x4.trans.shared.b16 {%0,%1,%2,%3}, [%4];" \
        : "=r"((r)[0]), "=r"((r)[1]), "=r"((r)[2]), "=r"((r)[3]) : "r"(addr))

__device__ __forceinline__ void mma_f16(float* c, const uint32_t* a,
                                        uint32_t b0, uint32_t b1) {
    asm volatile(
        "mma.sync.aligned.m16n8k16.row.col.f32.f16.f16.f32 "
        "{%0,%1,%2,%3},{%4,%5,%6,%7},{%8,%9},{%0,%1,%2,%3};\n"
        : "+f"(c[0]), "+f"(c[1]), "+f"(c[2]), "+f"(c[3])
        : "r"(a[0]), "r"(a[1]), "r"(a[2]), "r"(a[3]), "r"(b0), "r"(b1));
}

__device__ __forceinline__ void cpa16(uint32_t saddr, const void* src, bool v) {
    int sz = v ? 16 : 0;
    asm volatile("cp.async.cg.shared.global [%0], [%1], 16, %2;\n"
                 :: "r"(saddr), "l"(src), "r"(sz));
}

// ---------------- conversion kernels -------------------------------------------
__global__ void h_copy(const float* __restrict__ src, __half* __restrict__ dst, int n4) {
    int i = blockIdx.x * blockDim.x + threadIdx.x;
    if (i < n4) {
        float4 v = ((const float4*)src)[i];
        ((__half2*)dst)[2 * i]     = __floats2half2_rn(v.x, v.y);
        ((__half2*)dst)[2 * i + 1] = __floats2half2_rn(v.z, v.w);
    }
}

// q_up weights: head-interleave rows (h*192+d), fold scale*log2e, convert
#define QSC (0.07216878364870323f * 1.4426950408889634f)
__global__ void h_qup(const float* __restrict__ nope, const float* __restrict__ rope,
                      __half* __restrict__ dst) {
    int r = blockIdx.x;
    int h = r / 192, d = r - h * 192;
    const float* src = (d < 128) ? nope + (size_t)(h * 128 + d) * QLORA_
                                 : rope + (size_t)(h * 64 + d - 128) * QLORA_;
    __half* o = dst + (size_t)r * QLORA_;
    for (int i = threadIdx.x; i < QLORA_ / 4; i += 256) {
        float4 v = ((const float4*)src)[i];
        ((__half2*)o)[2 * i]     = __floats2half2_rn(v.x * QSC, v.y * QSC);
        ((__half2*)o)[2 * i + 1] = __floats2half2_rn(v.z * QSC, v.w * QSC);
    }
}

// ---------------- fp16 tensor-core GEMM: 256x128 CTA tile, 64x64 warp tile ------
// C[m,n] = sum_k A[m,k]*W[n,k]. M % 256 == 0, K % 32 == 0, N guarded per 64 rows.
// Optional fused RoPE epilogue (q_up).
#define HAS_B 80                      // bytes per smem row (32 halves + 8 pad)
#define A_TILE_B (256 * HAS_B)        // 20480
#define B_TILE_B (128 * HAS_B)        // 10240
#define HST_B (A_TILE_B + B_TILE_B)   // 30720
#define HST 4
#define HGEMM_SMEM (HST * HST_B)      // 122880

__global__ void __launch_bounds__(256, 1) hgemm(
    const __half* __restrict__ A, const __half* __restrict__ W,
    float* __restrict__ Cf, __half* __restrict__ Ch,
    int M, int N, int K, int ldc,
    int ropeOn, const float* __restrict__ fc, const float* __restrict__ fs)
{
    extern __shared__ __align__(16) char hsm[];
    uint32_t sbase = smem_u32(hsm);
    int tid = threadIdx.x, warp = tid >> 5, lane = tid & 31;
    int wm = warp >> 1, wn = warp & 1;
    int grp = lane >> 2, qid = lane & 3, lrow = lane & 15;
    int bm = blockIdx.y * 256, bn = blockIdx.x * 128;

    float acc[4][8][4];
#pragma unroll
    for (int mt = 0; mt < 4; mt++)
#pragma unroll
        for (int nt = 0; nt < 8; nt++)
#pragma unroll
            for (int i = 0; i < 4; i++) acc[mt][nt][i] = 0.f;

    int lr = tid >> 2, lc = tid & 3;
    const __half* Ag[4];
#pragma unroll
    for (int i = 0; i < 4; i++)
        Ag[i] = A + (size_t)(bm + lr + 64 * i) * K + lc * 8;
    int n0 = bn + lr, n1 = bn + lr + 64;
    bool v0 = n0 < N, v1 = n1 < N;
    const __half* Wg0 = W + (size_t)(v0 ? n0 : 0) * K + lc * 8;
    const __half* Wg1 = W + (size_t)(v1 ? n1 : 0) * K + lc * 8;
    uint32_t dA = sbase + lr * HAS_B + lc * 16;
    uint32_t dB0 = sbase + A_TILE_B + lr * HAS_B + lc * 16;
    uint32_t dB1 = dB0 + 64 * HAS_B;

    int NK = K >> 5;

    auto prefetch = [&](int kt) {
        uint32_t off = (uint32_t)((kt & (HST - 1)) * HST_B);
        int ko = kt * 32;
#pragma unroll
        for (int i = 0; i < 4; i++)
            cpa16(dA + off + (uint32_t)(64 * i * HAS_B), Ag[i] + ko, true);
        cpa16(dB0 + off, Wg0 + ko, v0);
        cpa16(dB1 + off, Wg1 + ko, v1);
    };

#pragma unroll
    for (int i = 0; i < HST - 1; i++) {
        if (i < NK) prefetch(i);
        asm volatile("cp.async.commit_group;\n");
    }

    for (int kt = 0; kt < NK; kt++) {
        asm volatile("cp.async.wait_group 2;\n");
        __syncthreads();
        if (kt + HST - 1 < NK) prefetch(kt + HST - 1);
        asm volatile("cp.async.commit_group;\n");

        uint32_t sA = sbase + (uint32_t)((kt & (HST - 1)) * HST_B);
        uint32_t sB = sA + A_TILE_B;
#pragma unroll
        for (int ks = 0; ks < 2; ks++) {
            uint32_t ko = (uint32_t)((ks * 16 + 8 * (lane >> 4)) * 2);
            uint32_t a[4][4], bfr[4][4];
#pragma unroll
            for (int mt = 0; mt < 4; mt++)
                LDMX4(a[mt], sA + (uint32_t)((wm * 64 + mt * 16 + lrow) * HAS_B) + ko);
#pragma unroll
            for (int p = 0; p < 4; p++)
                LDMX4(bfr[p], sB + (uint32_t)((wn * 64 + p * 16 + lrow) * HAS_B) + ko);
#pragma unroll
            for (int mt = 0; mt < 4; mt++)
#pragma unroll
                for (int nt = 0; nt < 8; nt++)
                    mma_f16(acc[mt][nt], a[mt],
                            bfr[nt >> 1][nt & 1], bfr[nt >> 1][(nt & 1) + 2]);
        }
    }

#pragma unroll
    for (int mt = 0; mt < 4; mt++) {
        int row = bm + wm * 64 + mt * 16 + grp;
        int t0r = row & (T_ - 1), t1r = (row + 8) & (T_ - 1);
#pragma unroll
        for (int nt = 0; nt < 8; nt++) {
            int n = bn + wn * 64 + nt * 8 + 2 * qid;
            if (n < N) {
                float o0 = acc[mt][nt][0], o1 = acc[mt][nt][1];
                float o2 = acc[mt][nt][2], o3 = acc[mt][nt][3];
                if (ropeOn) {
                    int d = n % 192;
                    if (d >= 128) {
                        int i = (d - 128) >> 1;
                        float c0 = fc[t0r * 32 + i], s0 = fs[t0r * 32 + i];
                        float c1 = fc[t1r * 32 + i], s1 = fs[t1r * 32 + i];
                        float a0 = o0 * c0 - o1 * s0, a1 = o0 * s0 + o1 * c0;
                        float a2 = o2 * c1 - o3 * s1, a3 = o2 * s1 + o3 * c1;
                        o0 = a0; o1 = a1; o2 = a2; o3 = a3;
                    }
                }
                if (Cf) {
                    *(float2*)&Cf[(size_t)row * ldc + n] = make_float2(o0, o1);
                    *(float2*)&Cf[(size_t)(row + 8) * ldc + n] = make_float2(o2, o3);
                } else {
                    *(__half2*)&Ch[(size_t)row * ldc + n] = __floats2half2_rn(o0, o1);
                    *(__half2*)&Ch[(size_t)(row + 8) * ldc + n] = __floats2half2_rn(o2, o3);
                }
            }
        }
    }
}

// ---------------- rmsnorm in place on half --------------------------------------
__global__ void rmsnorm_h(__half* __restrict__ io, const float* __restrict__ w, int D) {
    size_t row = blockIdx.x;
    __half* p = io + row * (size_t)D;
    float ss = 0.f;
    for (int i = threadIdx.x; i < D; i += 256) {
        float v = __half2float(p[i]); ss += v * v;
    }
    ss = block_reduce_sum_256(ss);
    float r = rsqrtf(ss / (float)D + 1e-6f);
    for (int i = threadIdx.x; i < D; i += 256)
        p[i] = __float2half_rn(__half2float(p[i]) * r * w[i]);
}

// ---------------- kv prep (half in): rmsnorm 512 -> ckv; rope 64 -> krope -------
__global__ void kvprep_h(const __half* __restrict__ raw, const float* __restrict__ w,
                         const float* __restrict__ fc, const float* __restrict__ fs,
                         __half* __restrict__ ckv, __half* __restrict__ kr) {
    int tok = blockIdx.x;
    const __half* src = raw + (size_t)tok * 576;
    float ss = 0.f;
    for (int i = threadIdx.x; i < 512; i += 256) {
        float v = __half2float(src[i]); ss += v * v;
    }
    ss = block_reduce_sum_256(ss);
    float r = rsqrtf(ss / 512.f + 1e-6f);
    for (int i = threadIdx.x; i < 512; i += 256)
        ckv[(size_t)tok * 512 + i] = __float2half_rn(__half2float(src[i]) * r * w[i]);
    if (threadIdx.x < 32) {
        int t = tok & (T_ - 1);
        int i = threadIdx.x;
        float x0 = __half2float(src[512 + 2 * i]);
        float x1 = __half2float(src[512 + 2 * i + 1]);
        float c = fc[t * 32 + i], s = fs[t * 32 + i];
        ((__half2*)kr)[(size_t)tok * 32 + i] =
            __floats2half2_rn(x0 * c - x1 * s, x0 * s + x1 * c);
    }
}

// ---------------- fp16 flash attention, Br=128, Bc=64, register P --------------
#define AQ 200    // halves per Q/K row (192+8); 400B stride
#define AK 200
#define AV 136    // 128+8
#define ATT_SMEM ((128*AQ + 2*64*AK + 2*64*AV) * 2)

__global__ void __launch_bounds__(256) attn2_kernel(
    const __half* __restrict__ qh, const __half* __restrict__ kvh,
    const __half* __restrict__ kroph, __half* __restrict__ out)
{
    extern __shared__ __align__(16) char smraw[];
    __half* hQ = (__half*)smraw;           // [128][AQ]
    __half* hK = hQ + 128 * AQ;            // [2][64][AK]
    __half* hV = hK + 2 * 64 * AK;         // [2][64][AV]
    uint32_t uQ = smem_u32(hQ), uK = smem_u32(hK), uV = smem_u32(hV);

    int b = blockIdx.z, h = blockIdx.y;
    int qblk = gridDim.x - 1 - blockIdx.x;   // big-work CTAs first
    int tid = threadIdx.x;
    int warp = tid >> 5, lane = tid & 31;
    int grp = lane >> 2, qid = lane & 3, lrow = lane & 15;
    int w16 = warp * 16;
    int t0 = b * T_ + qblk * 128;
    int r0 = w16 + grp, r1 = r0 + 8;

    auto prefKV = [&](int jt) {
        int kb = b * T_ + jt * 64;
        int s = jt & 1;
        uint32_t bK = uK + (uint32_t)(s * 64 * AK * 2);
        uint32_t bV = uV + (uint32_t)(s * 64 * AV * 2);
#pragma unroll
        for (int i = 0; i < 4; i++) {      // K nope
            int idx = tid + i * 256, c = idx >> 4, f = idx & 15;
            cpa16(bK + (uint32_t)((c * AK + f * 8) * 2),
                  kvh + (size_t)(kb + c) * 4096 + h * 256 + f * 8, true);
        }
#pragma unroll
        for (int i = 0; i < 2; i++) {      // K rope
            int idx = tid + i * 256, c = idx >> 3, f = idx & 7;
            cpa16(bK + (uint32_t)((c * AK + 128 + f * 8) * 2),
                  kroph + (size_t)(kb + c) * 64 + f * 8, true);
        }
#pragma unroll
        for (int i = 0; i < 4; i++) {      // V
            int idx = tid + i * 256, c = idx >> 4, f = idx & 15;
            cpa16(bV + (uint32_t)((c * AV + f * 8) * 2),
                  kvh + (size_t)(kb + c) * 4096 + h * 256 + 128 + f * 8, true);
        }
    };

    int jend = 2 * qblk + 1;
    prefKV(0);
    asm volatile("cp.async.commit_group;\n");

    // Q tile [128 x 192]
    for (int idx = tid; idx < 128 * 24; idx += 256) {
        int r = idx / 24, f = idx - r * 24;
        *(uint4*)&hQ[r * AQ + f * 8] =
            *(const uint4*)&qh[(size_t)(t0 + r) * 3072 + h * 192 + f * 8];
    }

    float m0 = -1e30f, m1 = -1e30f, l0 = 0.f, l1 = 0.f;
    float accO[16][4];
#pragma unroll
    for (int nt = 0; nt < 16; nt++)
#pragma unroll
        for (int i = 0; i < 4; i++) accO[nt][i] = 0.f;

    for (int jt = 0; jt <= jend; jt++) {
        __syncthreads();                       // prev iter done with s^1 buffer (+iter0: Q stores)
        if (jt < jend) prefKV(jt + 1);
        asm volatile("cp.async.commit_group;\n");
        if (jt < jend) { asm volatile("cp.async.wait_group 1;\n"); }
        else           { asm volatile("cp.async.wait_group 0;\n"); }
        __syncthreads();                       // tile jt visible

        int s = jt & 1;
        uint32_t bK = uK + (uint32_t)(s * 64 * AK * 2);
        uint32_t bV = uV + (uint32_t)(s * 64 * AV * 2);

        // S = Q K^T (warp tile 16x64)
        float sfr[8][4];
#pragma unroll
        for (int nt = 0; nt < 8; nt++)
#pragma unroll
            for (int i = 0; i < 4; i++) sfr[nt][i] = 0.f;
#pragma unroll
        for (int ks = 0; ks < 12; ks++) {
            uint32_t ko = (uint32_t)((ks * 16 + 8 * (lane >> 4)) * 2);
            uint32_t a[4], bfr[4][4];
            LDMX4(a, uQ + (uint32_t)((w16 + lrow) * AQ * 2) + ko);
#pragma unroll
            for (int p = 0; p < 4; p++)
                LDMX4(bfr[p], bK + (uint32_t)((p * 16 + lrow) * AK * 2) + ko);
#pragma unroll
            for (int nt = 0; nt < 8; nt++)
                mma_f16(sfr[nt], a, bfr[nt >> 1][nt & 1], bfr[nt >> 1][(nt & 1) + 2]);
        }

        // causal mask (last two tiles)
        if (jt >= jend - 1) {
            int coff = jt * 64 - qblk * 128;
#pragma unroll
            for (int nt = 0; nt < 8; nt++) {
                int c0 = coff + nt * 8 + 2 * qid;
                if (c0 > r0)     sfr[nt][0] = -1e30f;
                if (c0 + 1 > r0) sfr[nt][1] = -1e30f;
                if (c0 > r1)     sfr[nt][2] = -1e30f;
                if (c0 + 1 > r1) sfr[nt][3] = -1e30f;
            }
        }

        // in-warp row max
        float mx0 = -1e30f, mx1 = -1e30f;
#pragma unroll
        for (int nt = 0; nt < 8; nt++) {
            mx0 = fmaxf(mx0, fmaxf(sfr[nt][0], sfr[nt][1]));
            mx1 = fmaxf(mx1, fmaxf(sfr[nt][2], sfr[nt][3]));
        }
        mx0 = fmaxf(mx0, __shfl_xor_sync(0xffffffffu, mx0, 1));
        mx0 = fmaxf(mx0, __shfl_xor_sync(0xffffffffu, mx0, 2));
        mx1 = fmaxf(mx1, __shfl_xor_sync(0xffffffffu, mx1, 1));
        mx1 = fmaxf(mx1, __shfl_xor_sync(0xffffffffu, mx1, 2));
        float mn0 = fmaxf(m0, mx0), mn1 = fmaxf(m1, mx1);
        float al0 = ex2(m0 - mn0), al1 = ex2(m1 - mn1);
        m0 = mn0; m1 = mn1;

        // exp -> register-resident P operands (FA2 layout match)
        uint32_t hp0[8], hp1[8];
        float sum0 = 0.f, sum1 = 0.f;
#pragma unroll
        for (int nt = 0; nt < 8; nt++) {
            float p00 = ex2(sfr[nt][0] - mn0), p01 = ex2(sfr[nt][1] - mn0);
            float p10 = ex2(sfr[nt][2] - mn1), p11 = ex2(sfr[nt][3] - mn1);
            sum0 += p00 + p01;
            sum1 += p10 + p11;
            hp0[nt] = packh2(p00, p01);
            hp1[nt] = packh2(p10, p11);
        }
        sum0 += __shfl_xor_sync(0xffffffffu, sum0, 1);
        sum0 += __shfl_xor_sync(0xffffffffu, sum0, 2);
        sum1 += __shfl_xor_sync(0xffffffffu, sum1, 1);
        sum1 += __shfl_xor_sync(0xffffffffu, sum1, 2);
        l0 = l0 * al0 + sum0;
        l1 = l1 * al1 + sum1;

#pragma unroll
        for (int nt = 0; nt < 16; nt++) {
            accO[nt][0] *= al0; accO[nt][1] *= al0;
            accO[nt][2] *= al1; accO[nt][3] *= al1;
        }

        // O += P V (warp tile 16x128); P from registers, V via ldmatrix.trans
        int g = lane >> 3, ii = lane & 7;
#pragma unroll
        for (int ks = 0; ks < 4; ks++) {
            uint32_t pa[4] = { hp0[2 * ks], hp1[2 * ks],
                               hp0[2 * ks + 1], hp1[2 * ks + 1] };
#pragma unroll
            for (int np = 0; np < 8; np++) {
                uint32_t vb[4];
                LDMX4T(vb, bV + (uint32_t)(((ks * 16 + (g & 1) * 8 + ii) * AV
                                  + np * 16 + (g >> 1) * 8) * 2));
                mma_f16(accO[np * 2],     pa, vb[0], vb[1]);
                mma_f16(accO[np * 2 + 1], pa, vb[2], vb[3]);
            }
        }
    }

    float inv0 = 1.f / l0, inv1 = 1.f / l1;
#pragma unroll
    for (int nt = 0; nt < 16; nt++) {
        int col = h * 128 + nt * 8 + 2 * qid;
        *(__half2*)&out[(size_t)(t0 + r0) * 2048 + col] =
            __floats2half2_rn(accO[nt][0] * inv0, accO[nt][1] * inv0);
        *(__half2*)&out[(size_t)(t0 + r1) * 2048 + col] =
            __floats2half2_rn(accO[nt][2] * inv1, accO[nt][3] * inv1);
    }
}

// ---------------- launch -------------------------------------------------------
extern "C" void kernel_launch(void* const* d_in, const int* in_sizes, int n_in,
                              void* d_out, int out_size) {
    const float* x           = (const float*)d_in[0];
    const float* fc          = (const float*)d_in[1];
    const float* fs          = (const float*)d_in[2];
    const float* q_down_w    = (const float*)d_in[4];
    const float* q_norm_w    = (const float*)d_in[5];
    const float* q_up_nope_w = (const float*)d_in[6];
    const float* q_up_rope_w = (const float*)d_in[7];
    const float* kv_down_w   = (const float*)d_in[8];
    const float* kv_norm_w   = (const float*)d_in[9];
    const float* kv_up_w     = (const float*)d_in[10];
    const float* wo_w        = (const float*)d_in[11];
    float* out = (float*)d_out;

    __half *xh, *cqh, *kvrawh, *ckvh, *qh, *kroph, *kvh, *attnoh;
    __half *wqd, *wkd, *wqu, *wku, *wwo;
    cudaGetSymbolAddress((void**)&xh,     g_xh);
    cudaGetSymbolAddress((void**)&cqh,    g_cqh);
    cudaGetSymbolAddress((void**)&kvrawh, g_kvrawh);
    cudaGetSymbolAddress((void**)&ckvh,   g_ckvh);
    cudaGetSymbolAddress((void**)&qh,     g_qh);
    cudaGetSymbolAddress((void**)&kroph,  g_kropeh);
    cudaGetSymbolAddress((void**)&kvh,    g_kvh);
    cudaGetSymbolAddress((void**)&attnoh, g_attnoh);
    cudaGetSymbolAddress((void**)&wqd,    g_wqd);
    cudaGetSymbolAddress((void**)&wkd,    g_wkd);
    cudaGetSymbolAddress((void**)&wqu,    g_wqu);
    cudaGetSymbolAddress((void**)&wku,    g_wku);
    cudaGetSymbolAddress((void**)&wwo,    g_wwo);

    cudaFuncSetAttribute(hgemm, cudaFuncAttributeMaxDynamicSharedMemorySize, HGEMM_SMEM);
    cudaFuncSetAttribute(attn2_kernel, cudaFuncAttributeMaxDynamicSharedMemorySize, ATT_SMEM);

    auto hc = [&](const float* s, __half* d, size_t n) {
        int n4 = (int)(n / 4);
        h_copy<<<(n4 + 255) / 256, 256>>>(s, d, n4);
    };
    hc(x, xh, (size_t)MTOK * DIM_);
    hc(q_down_w, wqd, (size_t)QLORA_ * DIM_);
    hc(kv_down_w, wkd, (size_t)576 * DIM_);
    h_qup<<<3072, 256>>>(q_up_nope_w, q_up_rope_w, wqu);
    hc(kv_up_w, wku, (size_t)4096 * KVLORA_);
    hc(wo_w, wwo, (size_t)DIM_ * 2048);

    dim3 blk(256);
    // q_down -> half cqh; rmsnorm in place
    hgemm<<<dim3(1536 / 128, MTOK / 256), blk, HGEMM_SMEM>>>(
        xh, wqd, nullptr, cqh, MTOK, QLORA_, DIM_, QLORA_, 0, nullptr, nullptr);
    rmsnorm_h<<<MTOK, 256>>>(cqh, q_norm_w, QLORA_);

    // kv_down -> half kvrawh (N=576, guarded)
    hgemm<<<dim3(5, MTOK / 256), blk, HGEMM_SMEM>>>(
        xh, wkd, nullptr, kvrawh, MTOK, 576, DIM_, 576, 0, nullptr, nullptr);
    kvprep_h<<<MTOK, 256>>>(kvrawh, kv_norm_w, fc, fs, ckvh, kroph);

    // merged q_up -> half qh with FUSED RoPE epilogue
    hgemm<<<dim3(3072 / 128, MTOK / 256), blk, HGEMM_SMEM>>>(
        cqh, wqu, nullptr, qh, MTOK, 3072, QLORA_, 3072, 1, fc, fs);

    // kv_up -> half kvh
    hgemm<<<dim3(4096 / 128, MTOK / 256), blk, HGEMM_SMEM>>>(
        ckvh, wku, nullptr, kvh, MTOK, 4096, KVLORA_, 4096, 0, nullptr, nullptr);

    // attention -> half attno
    attn2_kernel<<<dim3(T_ / 128, H_, B_), 256, ATT_SMEM>>>(qh, kvh, kroph, attnoh);

    // wo -> f32 out
    hgemm<<<dim3(2048 / 128, MTOK / 256), blk, HGEMM_SMEM>>>(
        attnoh, wwo, out, nullptr, MTOK, 2048, 2048, 2048, 0, nullptr, nullptr);
}

// round 11
// speedup vs baseline: 1.1893x; 1.1893x over previous
#include <cuda_runtime.h>
#include <cuda_fp16.h>
#include <cstdint>

// Problem constants
#define B_ 4
#define T_ 2048
#define DIM_ 2048
#define H_ 16
#define QLORA_ 1536
#define KVLORA_ 512
#define MTOK (B_ * T_)   // 8192
#define NQKV 2112        // merged q_down(1536) + kv_down(576) output width

// ---------------- scratch (device globals; no runtime allocation) -------------
__device__ __half g_xh[(size_t)MTOK * DIM_];
__device__ __half g_cqkv[(size_t)MTOK * NQKV];        // merged: [cq 1536 | kvraw 576]
__device__ __half g_ckvh[(size_t)MTOK * KVLORA_];
__device__ __half g_qh[(size_t)MTOK * 3072];          // q_up out (half, scaled, roped)
__device__ __half g_kropeh[(size_t)MTOK * 64];
__device__ __half g_kvh[(size_t)MTOK * 4096];         // per head [K128|V128]
__device__ __half g_attnoh[(size_t)MTOK * 2048];
__device__ __half g_wqkd[(size_t)NQKV * DIM_];        // merged q_down + kv_down weights
__device__ __half g_wqu[(size_t)3072 * QLORA_];       // head-interleaved, pre-scaled
__device__ __half g_wku[(size_t)4096 * KVLORA_];
__device__ __half g_wwo[(size_t)DIM_ * 2048];

// ---------------- helpers ------------------------------------------------------
__device__ __forceinline__ float block_reduce_sum_256(float v) {
    __shared__ float red[8];
    int lane = threadIdx.x & 31, w = threadIdx.x >> 5;
#pragma unroll
    for (int o = 16; o; o >>= 1) v += __shfl_xor_sync(0xffffffffu, v, o);
    if (lane == 0) red[w] = v;
    __syncthreads();
    if (w == 0) {
        v = (lane < 8) ? red[lane] : 0.f;
#pragma unroll
        for (int o = 4; o; o >>= 1) v += __shfl_xor_sync(0xffffffffu, v, o);
        if (lane == 0) red[0] = v;
    }
    __syncthreads();
    return red[0];
}

__device__ __forceinline__ float ex2(float x) {
    float r;
    asm("ex2.approx.ftz.f32 %0, %1;" : "=f"(r) : "f"(x));
    return r;
}
__device__ __forceinline__ uint32_t smem_u32(const void* p) {
    uint32_t a;
    asm("{ .reg .u64 t; cvta.to.shared.u64 t, %1; cvt.u32.u64 %0, t; }"
        : "=r"(a) : "l"(p));
    return a;
}
__device__ __forceinline__ uint32_t packh2(float a, float b) {
    __half2 h = __floats2half2_rn(a, b);
    return *(uint32_t*)&h;
}

#define LDMX4(r, addr) \
    asm volatile("ldmatrix.sync.aligned.m8n8.x4.shared.b16 {%0,%1,%2,%3}, [%4];" \
        : "=r"((r)[0]), "=r"((r)[1]), "=r"((r)[2]), "=r"((r)[3]) : "r"(addr))
#define LDMX4T(r, addr) \
    asm volatile("ldmatrix.sync.aligned.m8n8.x4.trans.shared.b16 {%0,%1,%2,%3}, [%4];" \
        : "=r"((r)[0]), "=r"((r)[1]), "=r"((r)[2]), "=r"((r)[3]) : "r"(addr))

__device__ __forceinline__ void mma_f16(float* c, const uint32_t* a,
                                        uint32_t b0, uint32_t b1) {
    asm volatile(
        "mma.sync.aligned.m16n8k16.row.col.f32.f16.f16.f32 "
        "{%0,%1,%2,%3},{%4,%5,%6,%7},{%8,%9},{%0,%1,%2,%3};\n"
        : "+f"(c[0]), "+f"(c[1]), "+f"(c[2]), "+f"(c[3])
        : "r"(a[0]), "r"(a[1]), "r"(a[2]), "r"(a[3]), "r"(b0), "r"(b1));
}

__device__ __forceinline__ void cpa16(uint32_t saddr, const void* src, bool v) {
    int sz = v ? 16 : 0;
    asm volatile("cp.async.cg.shared.global [%0], [%1], 16, %2;\n"
                 :: "r"(saddr), "l"(src), "r"(sz));
}

// ---------------- conversion kernels -------------------------------------------
__global__ void h_copy(const float* __restrict__ src, __half* __restrict__ dst, int n4) {
    int i = blockIdx.x * blockDim.x + threadIdx.x;
    if (i < n4) {
        float4 v = ((const float4*)src)[i];
        ((__half2*)dst)[2 * i]     = __floats2half2_rn(v.x, v.y);
        ((__half2*)dst)[2 * i + 1] = __floats2half2_rn(v.z, v.w);
    }
}

// merged down-proj weights: rows 0..1535 from q_down_w, rows 1536..2111 from kv_down_w
__global__ void h_wqkd(const float* __restrict__ qd, const float* __restrict__ kd,
                       __half* __restrict__ dst) {
    int r = blockIdx.x;   // 0..2111
    const float* src = (r < QLORA_) ? qd + (size_t)r * DIM_
                                    : kd + (size_t)(r - QLORA_) * DIM_;
    __half* o = dst + (size_t)r * DIM_;
    for (int i = threadIdx.x; i < DIM_ / 4; i += 256) {
        float4 v = ((const float4*)src)[i];
        ((__half2*)o)[2 * i]     = __floats2half2_rn(v.x, v.y);
        ((__half2*)o)[2 * i + 1] = __floats2half2_rn(v.z, v.w);
    }
}

// q_up weights: head-interleave rows (h*192+d), fold scale*log2e, convert
#define QSC (0.07216878364870323f * 1.4426950408889634f)
__global__ void h_qup(const float* __restrict__ nope, const float* __restrict__ rope,
                      __half* __restrict__ dst) {
    int r = blockIdx.x;
    int h = r / 192, d = r - h * 192;
    const float* src = (d < 128) ? nope + (size_t)(h * 128 + d) * QLORA_
                                 : rope + (size_t)(h * 64 + d - 128) * QLORA_;
    __half* o = dst + (size_t)r * QLORA_;
    for (int i = threadIdx.x; i < QLORA_ / 4; i += 256) {
        float4 v = ((const float4*)src)[i];
        ((__half2*)o)[2 * i]     = __floats2half2_rn(v.x * QSC, v.y * QSC);
        ((__half2*)o)[2 * i + 1] = __floats2half2_rn(v.z * QSC, v.w * QSC);
    }
}

// ---------------- fp16 tensor-core GEMM (128x128 CTA, occ 2, strided A) ---------
// C[m,n] = sum_k A[m,k]*W[n,k]; A row stride = lda (halves). M%128==0, K%32==0.
// Optional fused RoPE epilogue (q_up).
#define HAS 40                    // halves per smem row (32 + 8 pad) = 80 B
#define HTILE_B (128 * HAS * 2)   // 10240 B
#define HST_B (2 * HTILE_B)       // 20480 B
#define HST 4
#define HGEMM_SMEM (HST * HST_B)  // 81920 B

__global__ void __launch_bounds__(256, 2) hgemm(
    const __half* __restrict__ A, const __half* __restrict__ W,
    float* __restrict__ Cf, __half* __restrict__ Ch,
    int M, int N, int K, int ldc, int lda,
    int ropeOn, const float* __restrict__ fc, const float* __restrict__ fs)
{
    extern __shared__ __align__(16) char hsm[];
    uint32_t sbase = smem_u32(hsm);
    int tid = threadIdx.x, warp = tid >> 5, lane = tid & 31;
    int wm = warp >> 2, wn = warp & 3, grp = lane >> 2, qid = lane & 3;
    int bm = blockIdx.y * 128, bn = blockIdx.x * 128;

    float acc[4][4][4];
#pragma unroll
    for (int mt = 0; mt < 4; mt++)
#pragma unroll
        for (int nt = 0; nt < 4; nt++)
#pragma unroll
            for (int i = 0; i < 4; i++) acc[mt][nt][i] = 0.f;

    int lr = tid >> 2, lc = tid & 3;
    const __half* Ag0 = A + (size_t)(bm + lr) * lda + lc * 8;
    const __half* Ag1 = A + (size_t)(bm + lr + 64) * lda + lc * 8;
    int n0 = bn + lr, n1 = bn + lr + 64;
    bool v0 = n0 < N, v1 = n1 < N;
    const __half* Wg0 = W + (size_t)(v0 ? n0 : 0) * K + lc * 8;
    const __half* Wg1 = W + (size_t)(v1 ? n1 : 0) * K + lc * 8;
    uint32_t dA0 = sbase + lr * 80 + lc * 16;
    uint32_t dA1 = dA0 + 64 * 80;
    uint32_t dB0 = dA0 + HTILE_B;
    uint32_t dB1 = dB0 + 64 * 80;

    int NK = K >> 5;

    auto prefetch = [&](int kt) {
        uint32_t off = (uint32_t)((kt % HST) * HST_B);
        int ko = kt * 32;
        cpa16(dA0 + off, Ag0 + ko, true);
        cpa16(dA1 + off, Ag1 + ko, true);
        cpa16(dB0 + off, Wg0 + ko, v0);
        cpa16(dB1 + off, Wg1 + ko, v1);
    };

#pragma unroll
    for (int i = 0; i < HST - 1; i++) {
        if (i < NK) prefetch(i);
        asm volatile("cp.async.commit_group;\n");
    }

    int lrow = lane & 15;
    for (int kt = 0; kt < NK; kt++) {
        asm volatile("cp.async.wait_group 2;\n");
        __syncthreads();
        if (kt + HST - 1 < NK) prefetch(kt + HST - 1);
        asm volatile("cp.async.commit_group;\n");

        uint32_t sA = sbase + (uint32_t)((kt % HST) * HST_B);
        uint32_t sB = sA + HTILE_B;
#pragma unroll
        for (int ks = 0; ks < 2; ks++) {
            uint32_t ko = (uint32_t)((ks * 16 + 8 * (lane >> 4)) * 2);
            uint32_t a[4][4], bfr[2][4];
#pragma unroll
            for (int mt = 0; mt < 4; mt++)
                LDMX4(a[mt], sA + (uint32_t)((wm * 64 + mt * 16 + lrow) * 80) + ko);
#pragma unroll
            for (int p = 0; p < 2; p++)
                LDMX4(bfr[p], sB + (uint32_t)((wn * 32 + p * 16 + lrow) * 80) + ko);
#pragma unroll
            for (int mt = 0; mt < 4; mt++)
#pragma unroll
                for (int nt = 0; nt < 4; nt++)
                    mma_f16(acc[mt][nt], a[mt],
                            bfr[nt >> 1][nt & 1], bfr[nt >> 1][(nt & 1) + 2]);
        }
    }

#pragma unroll
    for (int mt = 0; mt < 4; mt++) {
        int row = bm + wm * 64 + mt * 16 + grp;
        int t0r = row & (T_ - 1), t1r = (row + 8) & (T_ - 1);
#pragma unroll
        for (int nt = 0; nt < 4; nt++) {
            int n = bn + wn * 32 + nt * 8 + 2 * qid;
            if (n < N) {
                float o0 = acc[mt][nt][0], o1 = acc[mt][nt][1];
                float o2 = acc[mt][nt][2], o3 = acc[mt][nt][3];
                if (ropeOn) {
                    int d = n % 192;
                    if (d >= 128) {
                        int i = (d - 128) >> 1;
                        float c0 = fc[t0r * 32 + i], s0 = fs[t0r * 32 + i];
                        float c1 = fc[t1r * 32 + i], s1 = fs[t1r * 32 + i];
                        float a0 = o0 * c0 - o1 * s0, a1 = o0 * s0 + o1 * c0;
                        float a2 = o2 * c1 - o3 * s1, a3 = o2 * s1 + o3 * c1;
                        o0 = a0; o1 = a1; o2 = a2; o3 = a3;
                    }
                }
                if (Cf) {
                    *(float2*)&Cf[(size_t)row * ldc + n] = make_float2(o0, o1);
                    *(float2*)&Cf[(size_t)(row + 8) * ldc + n] = make_float2(o2, o3);
                } else {
                    *(__half2*)&Ch[(size_t)row * ldc + n] = __floats2half2_rn(o0, o1);
                    *(__half2*)&Ch[(size_t)(row + 8) * ldc + n] = __floats2half2_rn(o2, o3);
                }
            }
        }
    }
}

// ---------------- rmsnorm in place on half (merged-buffer slice) ----------------
__global__ void rmsnorm_h(__half* __restrict__ io, const float* __restrict__ w,
                          int D, int stride) {
    size_t row = blockIdx.x;
    __half* p = io + row * (size_t)stride;
    float ss = 0.f;
    for (int i = threadIdx.x; i < D; i += 256) {
        float v = __half2float(p[i]); ss += v * v;
    }
    ss = block_reduce_sum_256(ss);
    float r = rsqrtf(ss / (float)D + 1e-6f);
    for (int i = threadIdx.x; i < D; i += 256)
        p[i] = __float2half_rn(__half2float(p[i]) * r * w[i]);
}

// ---------------- kv prep from merged buffer (cols 1536..2111) ------------------
__global__ void kvprep_h(const __half* __restrict__ merged, const float* __restrict__ w,
                         const float* __restrict__ fc, const float* __restrict__ fs,
                         __half* __restrict__ ckv, __half* __restrict__ kr) {
    int tok = blockIdx.x;
    const __half* src = merged + (size_t)tok * NQKV + QLORA_;
    float ss = 0.f;
    for (int i = threadIdx.x; i < 512; i += 256) {
        float v = __half2float(src[i]); ss += v * v;
    }
    ss = block_reduce_sum_256(ss);
    float r = rsqrtf(ss / 512.f + 1e-6f);
    for (int i = threadIdx.x; i < 512; i += 256)
        ckv[(size_t)tok * 512 + i] = __float2half_rn(__half2float(src[i]) * r * w[i]);
    if (threadIdx.x < 32) {
        int t = tok & (T_ - 1);
        int i = threadIdx.x;
        float x0 = __half2float(src[512 + 2 * i]);
        float x1 = __half2float(src[512 + 2 * i + 1]);
        float c = fc[t * 32 + i], s = fs[t * 32 + i];
        ((__half2*)kr)[(size_t)tok * 32 + i] =
            __floats2half2_rn(x0 * c - x1 * s, x0 * s + x1 * c);
    }
}

// ---------------- fp16 flash attention, Br=128, Bc=64, register P --------------
#define AQ 200    // halves per Q/K row (192+8); 400B stride
#define AK 200
#define AV 136    // 128+8
#define ATT_SMEM ((128*AQ + 2*64*AK + 2*64*AV) * 2)

__global__ void __launch_bounds__(256) attn2_kernel(
    const __half* __restrict__ qh, const __half* __restrict__ kvh,
    const __half* __restrict__ kroph, __half* __restrict__ out)
{
    extern __shared__ __align__(16) char smraw[];
    __half* hQ = (__half*)smraw;           // [128][AQ]
    __half* hK = hQ + 128 * AQ;            // [2][64][AK]
    __half* hV = hK + 2 * 64 * AK;         // [2][64][AV]
    uint32_t uQ = smem_u32(hQ), uK = smem_u32(hK), uV = smem_u32(hV);

    int b = blockIdx.z, h = blockIdx.y;
    int qblk = gridDim.x - 1 - blockIdx.x;   // big-work CTAs first
    int tid = threadIdx.x;
    int warp = tid >> 5, lane = tid & 31;
    int grp = lane >> 2, qid = lane & 3, lrow = lane & 15;
    int w16 = warp * 16;
    int t0 = b * T_ + qblk * 128;
    int r0 = w16 + grp, r1 = r0 + 8;

    auto prefKV = [&](int jt) {
        int kb = b * T_ + jt * 64;
        int s = jt & 1;
        uint32_t bK = uK + (uint32_t)(s * 64 * AK * 2);
        uint32_t bV = uV + (uint32_t)(s * 64 * AV * 2);
#pragma unroll
        for (int i = 0; i < 4; i++) {
            int idx = tid + i * 256, c = idx >> 4, f = idx & 15;
            cpa16(bK + (uint32_t)((c * AK + f * 8) * 2),
                  kvh + (size_t)(kb + c) * 4096 + h * 256 + f * 8, true);
        }
#pragma unroll
        for (int i = 0; i < 2; i++) {
            int idx = tid + i * 256, c = idx >> 3, f = idx & 7;
            cpa16(bK + (uint32_t)((c * AK + 128 + f * 8) * 2),
                  kroph + (size_t)(kb + c) * 64 + f * 8, true);
        }
#pragma unroll
        for (int i = 0; i < 4; i++) {
            int idx = tid + i * 256, c = idx >> 4, f = idx & 15;
            cpa16(bV + (uint32_t)((c * AV + f * 8) * 2),
                  kvh + (size_t)(kb + c) * 4096 + h * 256 + 128 + f * 8, true);
        }
    };

    int jend = 2 * qblk + 1;
    prefKV(0);
    asm volatile("cp.async.commit_group;\n");

    for (int idx = tid; idx < 128 * 24; idx += 256) {
        int r = idx / 24, f = idx - r * 24;
        *(uint4*)&hQ[r * AQ + f * 8] =
            *(const uint4*)&qh[(size_t)(t0 + r) * 3072 + h * 192 + f * 8];
    }

    float m0 = -1e30f, m1 = -1e30f, l0 = 0.f, l1 = 0.f;
    float accO[16][4];
#pragma unroll
    for (int nt = 0; nt < 16; nt++)
#pragma unroll
        for (int i = 0; i < 4; i++) accO[nt][i] = 0.f;

    for (int jt = 0; jt <= jend; jt++) {
        __syncthreads();
        if (jt < jend) prefKV(jt + 1);
        asm volatile("cp.async.commit_group;\n");
        if (jt < jend) { asm volatile("cp.async.wait_group 1;\n"); }
        else           { asm volatile("cp.async.wait_group 0;\n"); }
        __syncthreads();

        int s = jt & 1;
        uint32_t bK = uK + (uint32_t)(s * 64 * AK * 2);
        uint32_t bV = uV + (uint32_t)(s * 64 * AV * 2);

        float sfr[8][4];
#pragma unroll
        for (int nt = 0; nt < 8; nt++)
#pragma unroll
            for (int i = 0; i < 4; i++) sfr[nt][i] = 0.f;
#pragma unroll
        for (int ks = 0; ks < 12; ks++) {
            uint32_t ko = (uint32_t)((ks * 16 + 8 * (lane >> 4)) * 2);
            uint32_t a[4], bfr[4][4];
            LDMX4(a, uQ + (uint32_t)((w16 + lrow) * AQ * 2) + ko);
#pragma unroll
            for (int p = 0; p < 4; p++)
                LDMX4(bfr[p], bK + (uint32_t)((p * 16 + lrow) * AK * 2) + ko);
#pragma unroll
            for (int nt = 0; nt < 8; nt++)
                mma_f16(sfr[nt], a, bfr[nt >> 1][nt & 1], bfr[nt >> 1][(nt & 1) + 2]);
        }

        if (jt >= jend - 1) {
            int coff = jt * 64 - qblk * 128;
#pragma unroll
            for (int nt = 0; nt < 8; nt++) {
                int c0 = coff + nt * 8 + 2 * qid;
                if (c0 > r0)     sfr[nt][0] = -1e30f;
                if (c0 + 1 > r0) sfr[nt][1] = -1e30f;
                if (c0 > r1)     sfr[nt][2] = -1e30f;
                if (c0 + 1 > r1) sfr[nt][3] = -1e30f;
            }
        }

        float mx0 = -1e30f, mx1 = -1e30f;
#pragma unroll
        for (int nt = 0; nt < 8; nt++) {
            mx0 = fmaxf(mx0, fmaxf(sfr[nt][0], sfr[nt][1]));
            mx1 = fmaxf(mx1, fmaxf(sfr[nt][2], sfr[nt][3]));
        }
        mx0 = fmaxf(mx0, __shfl_xor_sync(0xffffffffu, mx0, 1));
        mx0 = fmaxf(mx0, __shfl_xor_sync(0xffffffffu, mx0, 2));
        mx1 = fmaxf(mx1, __shfl_xor_sync(0xffffffffu, mx1, 1));
        mx1 = fmaxf(mx1, __shfl_xor_sync(0xffffffffu, mx1, 2));
        float mn0 = fmaxf(m0, mx0), mn1 = fmaxf(m1, mx1);
        float al0 = ex2(m0 - mn0), al1 = ex2(m1 - mn1);
        m0 = mn0; m1 = mn1;

        uint32_t hp0[8], hp1[8];
        float sum0 = 0.f, sum1 = 0.f;
#pragma unroll
        for (int nt = 0; nt < 8; nt++) {
            float p00 = ex2(sfr[nt][0] - mn0), p01 = ex2(sfr[nt][1] - mn0);
            float p10 = ex2(sfr[nt][2] - mn1), p11 = ex2(sfr[nt][3] - mn1);
            sum0 += p00 + p01;
            sum1 += p10 + p11;
            hp0[nt] = packh2(p00, p01);
            hp1[nt] = packh2(p10, p11);
        }
        sum0 += __shfl_xor_sync(0xffffffffu, sum0, 1);
        sum0 += __shfl_xor_sync(0xffffffffu, sum0, 2);
        sum1 += __shfl_xor_sync(0xffffffffu, sum1, 1);
        sum1 += __shfl_xor_sync(0xffffffffu, sum1, 2);
        l0 = l0 * al0 + sum0;
        l1 = l1 * al1 + sum1;

#pragma unroll
        for (int nt = 0; nt < 16; nt++) {
            accO[nt][0] *= al0; accO[nt][1] *= al0;
            accO[nt][2] *= al1; accO[nt][3] *= al1;
        }

        int g = lane >> 3, ii = lane & 7;
#pragma unroll
        for (int ks = 0; ks < 4; ks++) {
            uint32_t pa[4] = { hp0[2 * ks], hp1[2 * ks],
                               hp0[2 * ks + 1], hp1[2 * ks + 1] };
#pragma unroll
            for (int np = 0; np < 8; np++) {
                uint32_t vb[4];
                LDMX4T(vb, bV + (uint32_t)(((ks * 16 + (g & 1) * 8 + ii) * AV
                                  + np * 16 + (g >> 1) * 8) * 2));
                mma_f16(accO[np * 2],     pa, vb[0], vb[1]);
                mma_f16(accO[np * 2 + 1], pa, vb[2], vb[3]);
            }
        }
    }

    float inv0 = 1.f / l0, inv1 = 1.f / l1;
#pragma unroll
    for (int nt = 0; nt < 16; nt++) {
        int col = h * 128 + nt * 8 + 2 * qid;
        *(__half2*)&out[(size_t)(t0 + r0) * 2048 + col] =
            __floats2half2_rn(accO[nt][0] * inv0, accO[nt][1] * inv0);
        *(__half2*)&out[(size_t)(t0 + r1) * 2048 + col] =
            __floats2half2_rn(accO[nt][2] * inv1, accO[nt][3] * inv1);
    }
}

// ---------------- launch -------------------------------------------------------
extern "C" void kernel_launch(void* const* d_in, const int* in_sizes, int n_in,
                              void* d_out, int out_size) {
    const float* x           = (const float*)d_in[0];
    const float* fc          = (const float*)d_in[1];
    const float* fs          = (const float*)d_in[2];
    const float* q_down_w    = (const float*)d_in[4];
    const float* q_norm_w    = (const float*)d_in[5];
    const float* q_up_nope_w = (const float*)d_in[6];
    const float* q_up_rope_w = (const float*)d_in[7];
    const float* kv_down_w   = (const float*)d_in[8];
    const float* kv_norm_w   = (const float*)d_in[9];
    const float* kv_up_w     = (const float*)d_in[10];
    const float* wo_w        = (const float*)d_in[11];
    float* out = (float*)d_out;

    __half *xh, *cqkv, *ckvh, *qh, *kroph, *kvh, *attnoh;
    __half *wqkd, *wqu, *wku, *wwo;
    cudaGetSymbolAddress((void**)&xh,     g_xh);
    cudaGetSymbolAddress((void**)&cqkv,   g_cqkv);
    cudaGetSymbolAddress((void**)&ckvh,   g_ckvh);
    cudaGetSymbolAddress((void**)&qh,     g_qh);
    cudaGetSymbolAddress((void**)&kroph,  g_kropeh);
    cudaGetSymbolAddress((void**)&kvh,    g_kvh);
    cudaGetSymbolAddress((void**)&attnoh, g_attnoh);
    cudaGetSymbolAddress((void**)&wqkd,   g_wqkd);
    cudaGetSymbolAddress((void**)&wqu,    g_wqu);
    cudaGetSymbolAddress((void**)&wku,    g_wku);
    cudaGetSymbolAddress((void**)&wwo,    g_wwo);

    cudaFuncSetAttribute(hgemm, cudaFuncAttributeMaxDynamicSharedMemorySize, HGEMM_SMEM);
    cudaFuncSetAttribute(attn2_kernel, cudaFuncAttributeMaxDynamicSharedMemorySize, ATT_SMEM);

    auto hc = [&](const float* s, __half* d, size_t n) {
        int n4 = (int)(n / 4);
        h_copy<<<(n4 + 255) / 256, 256>>>(s, d, n4);
    };
    hc(x, xh, (size_t)MTOK * DIM_);
    h_wqkd<<<NQKV, 256>>>(q_down_w, kv_down_w, wqkd);
    h_qup<<<3072, 256>>>(q_up_nope_w, q_up_rope_w, wqu);
    hc(kv_up_w, wku, (size_t)4096 * KVLORA_);
    hc(wo_w, wwo, (size_t)DIM_ * 2048);

    dim3 blk(256);
    // merged down-proj: N=2112 -> cqkv (cols 0..1535 cq | 1536..2111 kvraw)
    hgemm<<<dim3((NQKV + 127) / 128, MTOK / 128), blk, HGEMM_SMEM>>>(
        xh, wqkd, nullptr, cqkv, MTOK, NQKV, DIM_, NQKV, DIM_, 0, nullptr, nullptr);
    rmsnorm_h<<<MTOK, 256>>>(cqkv, q_norm_w, QLORA_, NQKV);
    kvprep_h<<<MTOK, 256>>>(cqkv, kv_norm_w, fc, fs, ckvh, kroph);

    // merged q_up: A = cqkv rows (stride NQKV), K = 1536, fused RoPE epilogue
    hgemm<<<dim3(3072 / 128, MTOK / 128), blk, HGEMM_SMEM>>>(
        cqkv, wqu, nullptr, qh, MTOK, 3072, QLORA_, 3072, NQKV, 1, fc, fs);

    // kv_up
    hgemm<<<dim3(4096 / 128, MTOK / 128), blk, HGEMM_SMEM>>>(
        ckvh, wku, nullptr, kvh, MTOK, 4096, KVLORA_, 4096, KVLORA_, 0, nullptr, nullptr);

    // attention
    attn2_kernel<<<dim3(T_ / 128, H_, B_), 256, ATT_SMEM>>>(qh, kvh, kroph, attnoh);

    // wo
    hgemm<<<dim3(2048 / 128, MTOK / 128), blk, HGEMM_SMEM>>>(
        attnoh, wwo, out, nullptr, MTOK, 2048, 2048, 2048, 2048, 0, nullptr, nullptr);
}

// round 12
// speedup vs baseline: 1.1929x; 1.0030x over previous
#include <cuda_runtime.h>
#include <cuda_fp16.h>
#include <cstdint>

// Problem constants
#define B_ 4
#define T_ 2048
#define DIM_ 2048
#define H_ 16
#define QLORA_ 1536
#define KVLORA_ 512
#define MTOK (B_ * T_)   // 8192
#define NQKV 2112        // merged q_down(1536) + kv_down(576) output width

// ---------------- scratch (device globals; no runtime allocation) -------------
__device__ __half g_xh[(size_t)MTOK * DIM_];
__device__ __half g_cqkv[(size_t)MTOK * NQKV];        // merged: [cq 1536 | kvraw 576]
__device__ __half g_ckvh[(size_t)MTOK * KVLORA_];
__device__ __half g_qh[(size_t)MTOK * 3072];          // q_up out (half, scaled, roped)
__device__ __half g_kropeh[(size_t)MTOK * 64];
__device__ __half g_kvh[(size_t)MTOK * 4096];         // per head [K128|V128]
__device__ __half g_attnoh[(size_t)MTOK * 2048];
__device__ __half g_wqkd[(size_t)NQKV * DIM_];        // merged q_down + kv_down weights
__device__ __half g_wqu[(size_t)3072 * QLORA_];       // head-interleaved, pre-scaled
__device__ __half g_wku[(size_t)4096 * KVLORA_];
__device__ __half g_wwo[(size_t)DIM_ * 2048];

// ---------------- helpers ------------------------------------------------------
__device__ __forceinline__ float block_reduce_sum_256(float v) {
    __shared__ float red[8];
    int lane = threadIdx.x & 31, w = threadIdx.x >> 5;
#pragma unroll
    for (int o = 16; o; o >>= 1) v += __shfl_xor_sync(0xffffffffu, v, o);
    if (lane == 0) red[w] = v;
    __syncthreads();
    if (w == 0) {
        v = (lane < 8) ? red[lane] : 0.f;
#pragma unroll
        for (int o = 4; o; o >>= 1) v += __shfl_xor_sync(0xffffffffu, v, o);
        if (lane == 0) red[0] = v;
    }
    __syncthreads();
    return red[0];
}

__device__ __forceinline__ float ex2(float x) {
    float r;
    asm("ex2.approx.ftz.f32 %0, %1;" : "=f"(r) : "f"(x));
    return r;
}
__device__ __forceinline__ uint32_t smem_u32(const void* p) {
    uint32_t a;
    asm("{ .reg .u64 t; cvta.to.shared.u64 t, %1; cvt.u32.u64 %0, t; }"
        : "=r"(a) : "l"(p));
    return a;
}
__device__ __forceinline__ uint32_t packh2(float a, float b) {
    __half2 h = __floats2half2_rn(a, b);
    return *(uint32_t*)&h;
}
__device__ __forceinline__ uint2 pack4(float4 v) {
    return make_uint2(packh2(v.x, v.y), packh2(v.z, v.w));
}

#define LDMX4(r, addr) \
    asm volatile("ldmatrix.sync.aligned.m8n8.x4.shared.b16 {%0,%1,%2,%3}, [%4];" \
        : "=r"((r)[0]), "=r"((r)[1]), "=r"((r)[2]), "=r"((r)[3]) : "r"(addr))
#define LDMX4T(r, addr) \
    asm volatile("ldmatrix.sync.aligned.m8n8.x4.trans.shared.b16 {%0,%1,%2,%3}, [%4];" \
        : "=r"((r)[0]), "=r"((r)[1]), "=r"((r)[2]), "=r"((r)[3]) : "r"(addr))

__device__ __forceinline__ void mma_f16(float* c, const uint32_t* a,
                                        uint32_t b0, uint32_t b1) {
    asm volatile(
        "mma.sync.aligned.m16n8k16.row.col.f32.f16.f16.f32 "
        "{%0,%1,%2,%3},{%4,%5,%6,%7},{%8,%9},{%0,%1,%2,%3};\n"
        : "+f"(c[0]), "+f"(c[1]), "+f"(c[2]), "+f"(c[3])
        : "r"(a[0]), "r"(a[1]), "r"(a[2]), "r"(a[3]), "r"(b0), "r"(b1));
}

__device__ __forceinline__ void cpa16(uint32_t saddr, const void* src, bool v) {
    int sz = v ? 16 : 0;
    asm volatile("cp.async.cg.shared.global [%0], [%1], 16, %2;\n"
                 :: "r"(saddr), "l"(src), "r"(sz));
}

// ---------------- conversion kernels (MLP-4, packed stores) ---------------------
// n4 (float4 count) must be divisible by 4*blockDim*gridDim; each thread does
// 4 independent grid-strided float4 loads -> 4 uint2 stores.
__global__ void h_copy4(const float* __restrict__ src, __half* __restrict__ dst,
                        int S /* = n4/4 */) {
    int i = blockIdx.x * blockDim.x + threadIdx.x;
    const float4* s4 = (const float4*)src;
    uint2* d2 = (uint2*)dst;
    float4 v0 = s4[i], v1 = s4[i + S], v2 = s4[i + 2 * S], v3 = s4[i + 3 * S];
    d2[i]         = pack4(v0);
    d2[i + S]     = pack4(v1);
    d2[i + 2 * S] = pack4(v2);
    d2[i + 3 * S] = pack4(v3);
}

// q_up weights: head-interleave rows (h*192+d), fold scale*log2e, convert.
// One row per block, 128 threads x 3 float4 (row = 1536 floats = 384 float4).
#define QSC (0.07216878364870323f * 1.4426950408889634f)
__global__ void h_qup(const float* __restrict__ nope, const float* __restrict__ rope,
                      __half* __restrict__ dst) {
    int r = blockIdx.x;
    int h = r / 192, d = r - h * 192;
    const float* src = (d < 128) ? nope + (size_t)(h * 128 + d) * QLORA_
                                 : rope + (size_t)(h * 64 + d - 128) * QLORA_;
    const float4* s4 = (const float4*)src;
    uint2* o2 = (uint2*)(dst + (size_t)r * QLORA_);
    int i = threadIdx.x;
    float4 v0 = s4[i], v1 = s4[i + 128], v2 = s4[i + 256];
    v0.x *= QSC; v0.y *= QSC; v0.z *= QSC; v0.w *= QSC;
    v1.x *= QSC; v1.y *= QSC; v1.z *= QSC; v1.w *= QSC;
    v2.x *= QSC; v2.y *= QSC; v2.z *= QSC; v2.w *= QSC;
    o2[i]       = pack4(v0);
    o2[i + 128] = pack4(v1);
    o2[i + 256] = pack4(v2);
}

// ---------------- fp16 tensor-core GEMM (128x128 CTA, occ 2, strided A) ---------
#define HAS 40                    // halves per smem row (32 + 8 pad) = 80 B
#define HTILE_B (128 * HAS * 2)   // 10240 B
#define HST_B (2 * HTILE_B)       // 20480 B
#define HST 4
#define HGEMM_SMEM (HST * HST_B)  // 81920 B

__global__ void __launch_bounds__(256, 2) hgemm(
    const __half* __restrict__ A, const __half* __restrict__ W,
    float* __restrict__ Cf, __half* __restrict__ Ch,
    int M, int N, int K, int ldc, int lda,
    int ropeOn, const float* __restrict__ fc, const float* __restrict__ fs)
{
    extern __shared__ __align__(16) char hsm[];
    uint32_t sbase = smem_u32(hsm);
    int tid = threadIdx.x, warp = tid >> 5, lane = tid & 31;
    int wm = warp >> 2, wn = warp & 3, grp = lane >> 2, qid = lane & 3;
    int bm = blockIdx.y * 128, bn = blockIdx.x * 128;

    float acc[4][4][4];
#pragma unroll
    for (int mt = 0; mt < 4; mt++)
#pragma unroll
        for (int nt = 0; nt < 4; nt++)
#pragma unroll
            for (int i = 0; i < 4; i++) acc[mt][nt][i] = 0.f;

    int lr = tid >> 2, lc = tid & 3;
    const __half* Ag0 = A + (size_t)(bm + lr) * lda + lc * 8;
    const __half* Ag1 = A + (size_t)(bm + lr + 64) * lda + lc * 8;
    int n0 = bn + lr, n1 = bn + lr + 64;
    bool v0 = n0 < N, v1 = n1 < N;
    const __half* Wg0 = W + (size_t)(v0 ? n0 : 0) * K + lc * 8;
    const __half* Wg1 = W + (size_t)(v1 ? n1 : 0) * K + lc * 8;
    uint32_t dA0 = sbase + lr * 80 + lc * 16;
    uint32_t dA1 = dA0 + 64 * 80;
    uint32_t dB0 = dA0 + HTILE_B;
    uint32_t dB1 = dB0 + 64 * 80;

    int NK = K >> 5;

    auto prefetch = [&](int kt) {
        uint32_t off = (uint32_t)((kt % HST) * HST_B);
        int ko = kt * 32;
        cpa16(dA0 + off, Ag0 + ko, true);
        cpa16(dA1 + off, Ag1 + ko, true);
        cpa16(dB0 + off, Wg0 + ko, v0);
        cpa16(dB1 + off, Wg1 + ko, v1);
    };

#pragma unroll
    for (int i = 0; i < HST - 1; i++) {
        if (i < NK) prefetch(i);
        asm volatile("cp.async.commit_group;\n");
    }

    int lrow = lane & 15;
    for (int kt = 0; kt < NK; kt++) {
        asm volatile("cp.async.wait_group 2;\n");
        __syncthreads();
        if (kt + HST - 1 < NK) prefetch(kt + HST - 1);
        asm volatile("cp.async.commit_group;\n");

        uint32_t sA = sbase + (uint32_t)((kt % HST) * HST_B);
        uint32_t sB = sA + HTILE_B;
#pragma unroll
        for (int ks = 0; ks < 2; ks++) {
            uint32_t ko = (uint32_t)((ks * 16 + 8 * (lane >> 4)) * 2);
            uint32_t a[4][4], bfr[2][4];
#pragma unroll
            for (int mt = 0; mt < 4; mt++)
                LDMX4(a[mt], sA + (uint32_t)((wm * 64 + mt * 16 + lrow) * 80) + ko);
#pragma unroll
            for (int p = 0; p < 2; p++)
                LDMX4(bfr[p], sB + (uint32_t)((wn * 32 + p * 16 + lrow) * 80) + ko);
#pragma unroll
            for (int mt = 0; mt < 4; mt++)
#pragma unroll
                for (int nt = 0; nt < 4; nt++)
                    mma_f16(acc[mt][nt], a[mt],
                            bfr[nt >> 1][nt & 1], bfr[nt >> 1][(nt & 1) + 2]);
        }
    }

#pragma unroll
    for (int mt = 0; mt < 4; mt++) {
        int row = bm + wm * 64 + mt * 16 + grp;
        int t0r = row & (T_ - 1), t1r = (row + 8) & (T_ - 1);
#pragma unroll
        for (int nt = 0; nt < 4; nt++) {
            int n = bn + wn * 32 + nt * 8 + 2 * qid;
            if (n < N) {
                float o0 = acc[mt][nt][0], o1 = acc[mt][nt][1];
                float o2 = acc[mt][nt][2], o3 = acc[mt][nt][3];
                if (ropeOn) {
                    int d = n % 192;
                    if (d >= 128) {
                        int i = (d - 128) >> 1;
                        float c0 = fc[t0r * 32 + i], s0 = fs[t0r * 32 + i];
                        float c1 = fc[t1r * 32 + i], s1 = fs[t1r * 32 + i];
                        float a0 = o0 * c0 - o1 * s0, a1 = o0 * s0 + o1 * c0;
                        float a2 = o2 * c1 - o3 * s1, a3 = o2 * s1 + o3 * c1;
                        o0 = a0; o1 = a1; o2 = a2; o3 = a3;
                    }
                }
                if (Cf) {
                    *(float2*)&Cf[(size_t)row * ldc + n] = make_float2(o0, o1);
                    *(float2*)&Cf[(size_t)(row + 8) * ldc + n] = make_float2(o2, o3);
                } else {
                    *(__half2*)&Ch[(size_t)row * ldc + n] = __floats2half2_rn(o0, o1);
                    *(__half2*)&Ch[(size_t)(row + 8) * ldc + n] = __floats2half2_rn(o2, o3);
                }
            }
        }
    }
}

// ---------------- rmsnorm in place on half (merged-buffer slice) ----------------
__global__ void rmsnorm_h(__half* __restrict__ io, const float* __restrict__ w,
                          int D, int stride) {
    size_t row = blockIdx.x;
    __half* p = io + row * (size_t)stride;
    float ss = 0.f;
    for (int i = threadIdx.x; i < D; i += 256) {
        float v = __half2float(p[i]); ss += v * v;
    }
    ss = block_reduce_sum_256(ss);
    float r = rsqrtf(ss / (float)D + 1e-6f);
    for (int i = threadIdx.x; i < D; i += 256)
        p[i] = __float2half_rn(__half2float(p[i]) * r * w[i]);
}

// ---------------- kv prep from merged buffer (cols 1536..2111) ------------------
__global__ void kvprep_h(const __half* __restrict__ merged, const float* __restrict__ w,
                         const float* __restrict__ fc, const float* __restrict__ fs,
                         __half* __restrict__ ckv, __half* __restrict__ kr) {
    int tok = blockIdx.x;
    const __half* src = merged + (size_t)tok * NQKV + QLORA_;
    float ss = 0.f;
    for (int i = threadIdx.x; i < 512; i += 256) {
        float v = __half2float(src[i]); ss += v * v;
    }
    ss = block_reduce_sum_256(ss);
    float r = rsqrtf(ss / 512.f + 1e-6f);
    for (int i = threadIdx.x; i < 512; i += 256)
        ckv[(size_t)tok * 512 + i] = __float2half_rn(__half2float(src[i]) * r * w[i]);
    if (threadIdx.x < 32) {
        int t = tok & (T_ - 1);
        int i = threadIdx.x;
        float x0 = __half2float(src[512 + 2 * i]);
        float x1 = __half2float(src[512 + 2 * i + 1]);
        float c = fc[t * 32 + i], s = fs[t * 32 + i];
        ((__half2*)kr)[(size_t)tok * 32 + i] =
            __floats2half2_rn(x0 * c - x1 * s, x0 * s + x1 * c);
    }
}

// ---------------- fp16 flash attention, Br=128, Bc=64, register P --------------
#define AQ 200    // halves per Q/K row (192+8); 400B stride
#define AK 200
#define AV 136    // 128+8
#define ATT_SMEM ((128*AQ + 2*64*AK + 2*64*AV) * 2)

__global__ void __launch_bounds__(256) attn2_kernel(
    const __half* __restrict__ qh, const __half* __restrict__ kvh,
    const __half* __restrict__ kroph, __half* __restrict__ out)
{
    extern __shared__ __align__(16) char smraw[];
    __half* hQ = (__half*)smraw;           // [128][AQ]
    __half* hK = hQ + 128 * AQ;            // [2][64][AK]
    __half* hV = hK + 2 * 64 * AK;         // [2][64][AV]
    uint32_t uQ = smem_u32(hQ), uK = smem_u32(hK), uV = smem_u32(hV);

    int b = blockIdx.z, h = blockIdx.y;
    int qblk = gridDim.x - 1 - blockIdx.x;   // big-work CTAs first
    int tid = threadIdx.x;
    int warp = tid >> 5, lane = tid & 31;
    int grp = lane >> 2, qid = lane & 3, lrow = lane & 15;
    int w16 = warp * 16;
    int t0 = b * T_ + qblk * 128;
    int r0 = w16 + grp, r1 = r0 + 8;

    auto prefKV = [&](int jt) {
        int kb = b * T_ + jt * 64;
        int s = jt & 1;
        uint32_t bK = uK + (uint32_t)(s * 64 * AK * 2);
        uint32_t bV = uV + (uint32_t)(s * 64 * AV * 2);
#pragma unroll
        for (int i = 0; i < 4; i++) {
            int idx = tid + i * 256, c = idx >> 4, f = idx & 15;
            cpa16(bK + (uint32_t)((c * AK + f * 8) * 2),
                  kvh + (size_t)(kb + c) * 4096 + h * 256 + f * 8, true);
        }
#pragma unroll
        for (int i = 0; i < 2; i++) {
            int idx = tid + i * 256, c = idx >> 3, f = idx & 7;
            cpa16(bK + (uint32_t)((c * AK + 128 + f * 8) * 2),
                  kroph + (size_t)(kb + c) * 64 + f * 8, true);
        }
#pragma unroll
        for (int i = 0; i < 4; i++) {
            int idx = tid + i * 256, c = idx >> 4, f = idx & 15;
            cpa16(bV + (uint32_t)((c * AV + f * 8) * 2),
                  kvh + (size_t)(kb + c) * 4096 + h * 256 + 128 + f * 8, true);
        }
    };

    int jend = 2 * qblk + 1;
    prefKV(0);
    asm volatile("cp.async.commit_group;\n");

    for (int idx = tid; idx < 128 * 24; idx += 256) {
        int r = idx / 24, f = idx - r * 24;
        *(uint4*)&hQ[r * AQ + f * 8] =
            *(const uint4*)&qh[(size_t)(t0 + r) * 3072 + h * 192 + f * 8];
    }

    float m0 = -1e30f, m1 = -1e30f, l0 = 0.f, l1 = 0.f;
    float accO[16][4];
#pragma unroll
    for (int nt = 0; nt < 16; nt++)
#pragma unroll
        for (int i = 0; i < 4; i++) accO[nt][i] = 0.f;

    for (int jt = 0; jt <= jend; jt++) {
        __syncthreads();
        if (jt < jend) prefKV(jt + 1);
        asm volatile("cp.async.commit_group;\n");
        if (jt < jend) { asm volatile("cp.async.wait_group 1;\n"); }
        else           { asm volatile("cp.async.wait_group 0;\n"); }
        __syncthreads();

        int s = jt & 1;
        uint32_t bK = uK + (uint32_t)(s * 64 * AK * 2);
        uint32_t bV = uV + (uint32_t)(s * 64 * AV * 2);

        float sfr[8][4];
#pragma unroll
        for (int nt = 0; nt < 8; nt++)
#pragma unroll
            for (int i = 0; i < 4; i++) sfr[nt][i] = 0.f;
#pragma unroll
        for (int ks = 0; ks < 12; ks++) {
            uint32_t ko = (uint32_t)((ks * 16 + 8 * (lane >> 4)) * 2);
            uint32_t a[4], bfr[4][4];
            LDMX4(a, uQ + (uint32_t)((w16 + lrow) * AQ * 2) + ko);
#pragma unroll
            for (int p = 0; p < 4; p++)
                LDMX4(bfr[p], bK + (uint32_t)((p * 16 + lrow) * AK * 2) + ko);
#pragma unroll
            for (int nt = 0; nt < 8; nt++)
                mma_f16(sfr[nt], a, bfr[nt >> 1][nt & 1], bfr[nt >> 1][(nt & 1) + 2]);
        }

        if (jt >= jend - 1) {
            int coff = jt * 64 - qblk * 128;
#pragma unroll
            for (int nt = 0; nt < 8; nt++) {
                int c0 = coff + nt * 8 + 2 * qid;
                if (c0 > r0)     sfr[nt][0] = -1e30f;
                if (c0 + 1 > r0) sfr[nt][1] = -1e30f;
                if (c0 > r1)     sfr[nt][2] = -1e30f;
                if (c0 + 1 > r1) sfr[nt][3] = -1e30f;
            }
        }

        float mx0 = -1e30f, mx1 = -1e30f;
#pragma unroll
        for (int nt = 0; nt < 8; nt++) {
            mx0 = fmaxf(mx0, fmaxf(sfr[nt][0], sfr[nt][1]));
            mx1 = fmaxf(mx1, fmaxf(sfr[nt][2], sfr[nt][3]));
        }
        mx0 = fmaxf(mx0, __shfl_xor_sync(0xffffffffu, mx0, 1));
        mx0 = fmaxf(mx0, __shfl_xor_sync(0xffffffffu, mx0, 2));
        mx1 = fmaxf(mx1, __shfl_xor_sync(0xffffffffu, mx1, 1));
        mx1 = fmaxf(mx1, __shfl_xor_sync(0xffffffffu, mx1, 2));
        float mn0 = fmaxf(m0, mx0), mn1 = fmaxf(m1, mx1);
        float al0 = ex2(m0 - mn0), al1 = ex2(m1 - mn1);
        m0 = mn0; m1 = mn1;

        uint32_t hp0[8], hp1[8];
        float sum0 = 0.f, sum1 = 0.f;
#pragma unroll
        for (int nt = 0; nt < 8; nt++) {
            float p00 = ex2(sfr[nt][0] - mn0), p01 = ex2(sfr[nt][1] - mn0);
            float p10 = ex2(sfr[nt][2] - mn1), p11 = ex2(sfr[nt][3] - mn1);
            sum0 += p00 + p01;
            sum1 += p10 + p11;
            hp0[nt] = packh2(p00, p01);
            hp1[nt] = packh2(p10, p11);
        }
        sum0 += __shfl_xor_sync(0xffffffffu, sum0, 1);
        sum0 += __shfl_xor_sync(0xffffffffu, sum0, 2);
        sum1 += __shfl_xor_sync(0xffffffffu, sum1, 1);
        sum1 += __shfl_xor_sync(0xffffffffu, sum1, 2);
        l0 = l0 * al0 + sum0;
        l1 = l1 * al1 + sum1;

#pragma unroll
        for (int nt = 0; nt < 16; nt++) {
            accO[nt][0] *= al0; accO[nt][1] *= al0;
            accO[nt][2] *= al1; accO[nt][3] *= al1;
        }

        int g = lane >> 3, ii = lane & 7;
#pragma unroll
        for (int ks = 0; ks < 4; ks++) {
            uint32_t pa[4] = { hp0[2 * ks], hp1[2 * ks],
                               hp0[2 * ks + 1], hp1[2 * ks + 1] };
#pragma unroll
            for (int np = 0; np < 8; np++) {
                uint32_t vb[4];
                LDMX4T(vb, bV + (uint32_t)(((ks * 16 + (g & 1) * 8 + ii) * AV
                                  + np * 16 + (g >> 1) * 8) * 2));
                mma_f16(accO[np * 2],     pa, vb[0], vb[1]);
                mma_f16(accO[np * 2 + 1], pa, vb[2], vb[3]);
            }
        }
    }

    float inv0 = 1.f / l0, inv1 = 1.f / l1;
#pragma unroll
    for (int nt = 0; nt < 16; nt++) {
        int col = h * 128 + nt * 8 + 2 * qid;
        *(__half2*)&out[(size_t)(t0 + r0) * 2048 + col] =
            __floats2half2_rn(accO[nt][0] * inv0, accO[nt][1] * inv0);
        *(__half2*)&out[(size_t)(t0 + r1) * 2048 + col] =
            __floats2half2_rn(accO[nt][2] * inv1, accO[nt][3] * inv1);
    }
}

// ---------------- launch -------------------------------------------------------
extern "C" void kernel_launch(void* const* d_in, const int* in_sizes, int n_in,
                              void* d_out, int out_size) {
    const float* x           = (const float*)d_in[0];
    const float* fc          = (const float*)d_in[1];
    const float* fs          = (const float*)d_in[2];
    const float* q_down_w    = (const float*)d_in[4];
    const float* q_norm_w    = (const float*)d_in[5];
    const float* q_up_nope_w = (const float*)d_in[6];
    const float* q_up_rope_w = (const float*)d_in[7];
    const float* kv_down_w   = (const float*)d_in[8];
    const float* kv_norm_w   = (const float*)d_in[9];
    const float* kv_up_w     = (const float*)d_in[10];
    const float* wo_w        = (const float*)d_in[11];
    float* out = (float*)d_out;

    __half *xh, *cqkv, *ckvh, *qh, *kroph, *kvh, *attnoh;
    __half *wqkd, *wqu, *wku, *wwo;
    cudaGetSymbolAddress((void**)&xh,     g_xh);
    cudaGetSymbolAddress((void**)&cqkv,   g_cqkv);
    cudaGetSymbolAddress((void**)&ckvh,   g_ckvh);
    cudaGetSymbolAddress((void**)&qh,     g_qh);
    cudaGetSymbolAddress((void**)&kroph,  g_kropeh);
    cudaGetSymbolAddress((void**)&kvh,    g_kvh);
    cudaGetSymbolAddress((void**)&attnoh, g_attnoh);
    cudaGetSymbolAddress((void**)&wqkd,   g_wqkd);
    cudaGetSymbolAddress((void**)&wqu,    g_wqu);
    cudaGetSymbolAddress((void**)&wku,    g_wku);
    cudaGetSymbolAddress((void**)&wwo,    g_wwo);

    cudaFuncSetAttribute(hgemm, cudaFuncAttributeMaxDynamicSharedMemorySize, HGEMM_SMEM);
    cudaFuncSetAttribute(attn2_kernel, cudaFuncAttributeMaxDynamicSharedMemorySize, ATT_SMEM);

    // high-MLP conversions (all sizes divisible by 4096 elements)
    auto hc4 = [&](const float* s, __half* d, size_t n) {
        int S = (int)(n / 16);              // float4 stride (= n4/4)
        h_copy4<<<S / 256, 256>>>(s, d, S);
    };
    hc4(x, xh, (size_t)MTOK * DIM_);
    hc4(q_down_w, wqkd, (size_t)QLORA_ * DIM_);                       // rows 0..1535
    hc4(kv_down_w, wqkd + (size_t)QLORA_ * DIM_, (size_t)576 * DIM_); // rows 1536..2111
    h_qup<<<3072, 128>>>(q_up_nope_w, q_up_rope_w, wqu);
    hc4(kv_up_w, wku, (size_t)4096 * KVLORA_);
    hc4(wo_w, wwo, (size_t)DIM_ * 2048);

    dim3 blk(256);
    // merged down-proj: N=2112 -> cqkv (cols 0..1535 cq | 1536..2111 kvraw)
    hgemm<<<dim3((NQKV + 127) / 128, MTOK / 128), blk, HGEMM_SMEM>>>(
        xh, wqkd, nullptr, cqkv, MTOK, NQKV, DIM_, NQKV, DIM_, 0, nullptr, nullptr);
    rmsnorm_h<<<MTOK, 256>>>(cqkv, q_norm_w, QLORA_, NQKV);
    kvprep_h<<<MTOK, 256>>>(cqkv, kv_norm_w, fc, fs, ckvh, kroph);

    // merged q_up: A = cqkv rows (stride NQKV), K = 1536, fused RoPE epilogue
    hgemm<<<dim3(3072 / 128, MTOK / 128), blk, HGEMM_SMEM>>>(
        cqkv, wqu, nullptr, qh, MTOK, 3072, QLORA_, 3072, NQKV, 1, fc, fs);

    // kv_up
    hgemm<<<dim3(4096 / 128, MTOK / 128), blk, HGEMM_SMEM>>>(
        ckvh, wku, nullptr, kvh, MTOK, 4096, KVLORA_, 4096, KVLORA_, 0, nullptr, nullptr);

    // attention
    attn2_kernel<<<dim3(T_ / 128, H_, B_), 256, ATT_SMEM>>>(qh, kvh, kroph, attnoh);

    // wo
    hgemm<<<dim3(2048 / 128, MTOK / 128), blk, HGEMM_SMEM>>>(
        attnoh, wwo, out, nullptr, MTOK, 2048, 2048, 2048, 2048, 0, nullptr, nullptr);
}